// round 10
// baseline (speedup 1.0000x reference)
#include <cuda_runtime.h>

// ProjectionLoss fused single-kernel, shared-fold + j-split:
//   Block = 8 batch elements x 256 threads. Thread = (b_local, view, j-quarter),
//   16 point-views each. The K-folded matrices (K@[R|t], K@cam) are computed
//   ONCE per (b,view) by 64 folder threads (from global) into smem; the 4
//   j-split threads sharing a view read them via broadcast LDS.128 -> high
//   occupancy (8 warps/block, 2048 blocks) WITHOUT duplicated fold overhead
//   (which caused the R7/R8 regressions).
//   Scalar matvec (18 FFMA/pv - packing movs proved a net loss twice).
//   Smooth-MSE: min(d2, ex2(fma(lg2(d2),0.1,log2(400^0.9)))), branch-free.
//   Tail: last-arriving block reduces per-block partials in fixed order.

#define B_TOTAL 16384
#define V_NUM   8
#define J_NUM   64
#define NB      8                         // batch elements per block
#define JSPLIT  4                         // j-split threads per (b,view)
#define THREADS (NB * V_NUM * JSPLIT)     // 256
#define NBLOCKS (B_TOTAL / NB)            // 2048
#define QUADS   (J_NUM / 4 / JSPLIT)      // 4 quads (16 joints) per thread

#define LOG2_POWC 7.77947056f             // log2(400^0.9)

__device__ float g_partials[NBLOCKS];
__device__ int   g_count = 0;

__device__ __forceinline__ float rcpa(float x) {
    float r; asm("rcp.approx.f32 %0, %1;" : "=f"(r) : "f"(x)); return r;
}
__device__ __forceinline__ float lg2a(float x) {
    float r; asm("lg2.approx.f32 %0, %1;" : "=f"(r) : "f"(x)); return r;
}
__device__ __forceinline__ float ex2a(float x) {
    float r; asm("ex2.approx.f32 %0, %1;" : "=f"(r) : "f"(x)); return r;
}
__device__ __forceinline__ float smooth_term(float d2) {
    // exact rewrite of: d2>400 ? d2^0.1 * 400^0.9 : d2 (pow branch >= d2 iff d2<=400)
    float p = ex2a(fmaf(lg2a(d2), 0.1f, LOG2_POWC));
    return fminf(d2, p);
}

__global__ __launch_bounds__(THREADS, 8)
void proj_loss_fused(const float* __restrict__ gt_kps,
                     const float* __restrict__ pr_kps,
                     const float* __restrict__ gt_R,
                     const float* __restrict__ gt_t,
                     const float* __restrict__ Kmat,
                     const float* __restrict__ cam,
                     float* __restrict__ out)
{
    __shared__ __align__(16) float sGT[NB * J_NUM * 3];          // 1536 floats
    __shared__ __align__(16) float sPR[NB * J_NUM * 3];          // 1536
    __shared__ __align__(16) float sFold[NB * V_NUM * 24];       // 1536 (24 f/record)
    __shared__ float sWarp[THREADS / 32];
    __shared__ int   sIsLast;

    const int tid = threadIdx.x;
    const long b0 = (long)blockIdx.x * NB;

    // ---- stage keypoints to smem (float4, guarded strided) ----
    {
        const float4* g = (const float4*)(gt_kps + b0 * (J_NUM * 3));
        float4* s = (float4*)sGT;
        for (int i = tid; i < NB * J_NUM * 3 / 4; i += THREADS) s[i] = g[i];
    }
    {
        const float4* g = (const float4*)(pr_kps + b0 * (J_NUM * 3));
        float4* s = (float4*)sPR;
        for (int i = tid; i < NB * J_NUM * 3 / 4; i += THREADS) s[i] = g[i];
    }

    // ---- fold phase: 64 threads compute K@[R|t] and K@cam ONCE per (b,v) ----
    if (tid < NB * V_NUM) {
        const int fbl = tid >> 3;       // 0..7
        const int fv  = tid & 7;        // 0..7
        const float* k  = Kmat + fv * 9;
        const float* R  = gt_R + (b0 + fbl) * (V_NUM * 9)  + fv * 9;
        const float* t  = gt_t + (b0 + fbl) * (V_NUM * 3)  + fv * 3;
        const float* cm = cam  + (b0 + fbl) * (V_NUM * 12) + fv * 12;
        float* rec = &sFold[tid * 24];
        #pragma unroll
        for (int r = 0; r < 3; r++) {
            float k0 = k[r * 3 + 0], k1 = k[r * 3 + 1], k2 = k[r * 3 + 2];
            #pragma unroll
            for (int c = 0; c < 3; c++)
                rec[r * 4 + c] = fmaf(k0, R[c], fmaf(k1, R[3 + c], k2 * R[6 + c]));
            rec[r * 4 + 3] = fmaf(k0, t[0], fmaf(k1, t[1], k2 * t[2]));
            #pragma unroll
            for (int c = 0; c < 4; c++)
                rec[12 + r * 4 + c] = fmaf(k0, cm[c], fmaf(k1, cm[4 + c], k2 * cm[8 + c]));
        }
    }
    __syncthreads();

    // ---- consumer mapping: bl | v | jh ----
    const int bl = tid >> 5;            // 0..7
    const int v  = (tid >> 2) & 7;      // 0..7
    const int jh = tid & 3;             // 0..3

    // load folded matrices from smem (broadcast among the 4 jh threads)
    float G[12], Cm[12];
    {
        const float4* rec4 = (const float4*)&sFold[((bl << 3) + v) * 24];
        #pragma unroll
        for (int i = 0; i < 3; i++) {
            float4 a = rec4[i];
            G[i * 4 + 0] = a.x; G[i * 4 + 1] = a.y; G[i * 4 + 2] = a.z; G[i * 4 + 3] = a.w;
        }
        #pragma unroll
        for (int i = 0; i < 3; i++) {
            float4 a = rec4[3 + i];
            Cm[i * 4 + 0] = a.x; Cm[i * 4 + 1] = a.y; Cm[i * 4 + 2] = a.z; Cm[i * 4 + 3] = a.w;
        }
    }

    const float4* gt4 = (const float4*)(sGT + bl * (J_NUM * 3));
    const float4* pr4 = (const float4*)(sPR + bl * (J_NUM * 3));

    float acc = 0.0f;

    // ---- main loop: this thread's 16 joints = 4 quads ----
    #pragma unroll
    for (int q = 0; q < QUADS; q++) {
        const int jq = jh * QUADS + q;
        const float4 xa = gt4[jq * 3 + 0];
        const float4 xb = gt4[jq * 3 + 1];
        const float4 xc = gt4[jq * 3 + 2];
        const float4 pa = pr4[jq * 3 + 0];
        const float4 pb = pr4[jq * 3 + 1];
        const float4 pc = pr4[jq * 3 + 2];

        const float Xs[4][3] = {{xa.x, xa.y, xa.z}, {xa.w, xb.x, xb.y},
                                {xb.z, xb.w, xc.x}, {xc.y, xc.z, xc.w}};
        const float Ps[4][3] = {{pa.x, pa.y, pa.z}, {pa.w, pb.x, pb.y},
                                {pb.z, pb.w, pc.x}, {pc.y, pc.z, pc.w}};

        #pragma unroll
        for (int s = 0; s < 4; s++) {
            const float X0 = Xs[s][0], X1 = Xs[s][1], X2 = Xs[s][2];
            const float P0 = Ps[s][0], P1 = Ps[s][1], P2 = Ps[s][2];

            float u  = fmaf(G[0], X0, fmaf(G[1], X1, fmaf(G[2],  X2, G[3])));
            float vv = fmaf(G[4], X0, fmaf(G[5], X1, fmaf(G[6],  X2, G[7])));
            float w  = fmaf(G[8], X0, fmaf(G[9], X1, fmaf(G[10], X2, G[11])));

            float up = fmaf(Cm[0], P0, fmaf(Cm[1], P1, fmaf(Cm[2],  P2, Cm[3])));
            float vp = fmaf(Cm[4], P0, fmaf(Cm[5], P1, fmaf(Cm[6],  P2, Cm[7])));
            float wp = fmaf(Cm[8], P0, fmaf(Cm[9], P1, fmaf(Cm[10], P2, Cm[11])));

            float r  = rcpa(w * wp);
            float nw = -w;
            float dx = fmaf(up, nw, u  * wp) * r;
            float dy = fmaf(vp, nw, vv * wp) * r;

            acc += smooth_term(dx * dx);
            acc += smooth_term(dy * dy);
        }
    }

    // ---- block reduction (8 warps) ----
    #pragma unroll
    for (int o = 16; o > 0; o >>= 1)
        acc += __shfl_xor_sync(0xFFFFFFFFu, acc, o);

    const int lane = tid & 31;
    const int wid  = tid >> 5;
    if (lane == 0) sWarp[wid] = acc;
    __syncthreads();

    if (wid == 0) {
        float s = (lane < THREADS / 32) ? sWarp[lane] : 0.0f;
        #pragma unroll
        for (int o = 4; o > 0; o >>= 1)
            s += __shfl_xor_sync(0xFFFFFFFFu, s, o);
        if (lane == 0) g_partials[blockIdx.x] = s;
    }

    // ---- fused finish: last-arriving block reduces partials ----
    __threadfence();
    if (tid == 0) {
        int c = atomicAdd(&g_count, 1);
        sIsLast = (c == NBLOCKS - 1);
    }
    __syncthreads();

    if (sIsLast) {
        float s = 0.0f;
        #pragma unroll
        for (int rep = 0; rep < NBLOCKS / THREADS; rep++)
            s += g_partials[tid + rep * THREADS];

        #pragma unroll
        for (int o = 16; o > 0; o >>= 1)
            s += __shfl_xor_sync(0xFFFFFFFFu, s, o);
        if (lane == 0) sWarp[wid] = s;
        __syncthreads();

        if (wid == 0) {
            float t = (lane < THREADS / 32) ? sWarp[lane] : 0.0f;
            #pragma unroll
            for (int o = 4; o > 0; o >>= 1)
                t += __shfl_xor_sync(0xFFFFFFFFu, t, o);
            if (lane == 0) {
                out[0] = t * (1.0f / (2.0f * (float)B_TOTAL));
                g_count = 0;   // reset for next graph replay
            }
        }
    }
}

extern "C" void kernel_launch(void* const* d_in, const int* in_sizes, int n_in,
                              void* d_out, int out_size)
{
    const float* gt_kps = (const float*)d_in[0];
    const float* pr_kps = (const float*)d_in[1];
    const float* gt_R   = (const float*)d_in[2];
    const float* gt_t   = (const float*)d_in[3];
    const float* Kmat   = (const float*)d_in[4];
    const float* cam    = (const float*)d_in[5];
    float* out = (float*)d_out;

    proj_loss_fused<<<NBLOCKS, THREADS>>>(gt_kps, pr_kps, gt_R, gt_t, Kmat, cam, out);
}

// round 11
// speedup vs baseline: 2.6257x; 2.6257x over previous
#include <cuda_runtime.h>

// ProjectionLoss fused single-kernel, shared-fold + j-split:
//   Block = 8 batch elements x 256 threads. Thread = (b_local, view, j-quarter),
//   16 point-views each. K-folded matrices (K@[R|t], K@cam) computed ONCE per
//   (b,view) by 64 folder threads into smem; 4 j-split threads per view read
//   them via broadcast LDS.128.
//   __launch_bounds__(256, 4): 64-reg budget. The previous round's (256, 8)
//   forced 32 regs -> spilled G/Cm to local memory -> 8x DRAM traffic, 76us.
//   Scalar matvec (18 FFMA/pv). Smooth-MSE branch-free min() form.
//   Tail: last-arriving block reduces per-block partials in fixed order.

#define B_TOTAL 16384
#define V_NUM   8
#define J_NUM   64
#define NB      8                         // batch elements per block
#define JSPLIT  4                         // j-split threads per (b,view)
#define THREADS (NB * V_NUM * JSPLIT)     // 256
#define NBLOCKS (B_TOTAL / NB)            // 2048
#define QUADS   (J_NUM / 4 / JSPLIT)      // 4 quads (16 joints) per thread

#define LOG2_POWC 7.77947056f             // log2(400^0.9)

__device__ float g_partials[NBLOCKS];
__device__ int   g_count = 0;

__device__ __forceinline__ float rcpa(float x) {
    float r; asm("rcp.approx.f32 %0, %1;" : "=f"(r) : "f"(x)); return r;
}
__device__ __forceinline__ float lg2a(float x) {
    float r; asm("lg2.approx.f32 %0, %1;" : "=f"(r) : "f"(x)); return r;
}
__device__ __forceinline__ float ex2a(float x) {
    float r; asm("ex2.approx.f32 %0, %1;" : "=f"(r) : "f"(x)); return r;
}
__device__ __forceinline__ float smooth_term(float d2) {
    // exact rewrite of: d2>400 ? d2^0.1 * 400^0.9 : d2 (pow branch >= d2 iff d2<=400)
    float p = ex2a(fmaf(lg2a(d2), 0.1f, LOG2_POWC));
    return fminf(d2, p);
}

__global__ __launch_bounds__(THREADS, 4)
void proj_loss_fused(const float* __restrict__ gt_kps,
                     const float* __restrict__ pr_kps,
                     const float* __restrict__ gt_R,
                     const float* __restrict__ gt_t,
                     const float* __restrict__ Kmat,
                     const float* __restrict__ cam,
                     float* __restrict__ out)
{
    __shared__ __align__(16) float sGT[NB * J_NUM * 3];          // 1536 floats
    __shared__ __align__(16) float sPR[NB * J_NUM * 3];          // 1536
    __shared__ __align__(16) float sFold[NB * V_NUM * 24];       // 1536 (24 f/record)
    __shared__ float sWarp[THREADS / 32];
    __shared__ int   sIsLast;

    const int tid = threadIdx.x;
    const long b0 = (long)blockIdx.x * NB;

    // ---- stage keypoints to smem (float4, guarded strided) ----
    {
        const float4* g = (const float4*)(gt_kps + b0 * (J_NUM * 3));
        float4* s = (float4*)sGT;
        for (int i = tid; i < NB * J_NUM * 3 / 4; i += THREADS) s[i] = g[i];
    }
    {
        const float4* g = (const float4*)(pr_kps + b0 * (J_NUM * 3));
        float4* s = (float4*)sPR;
        for (int i = tid; i < NB * J_NUM * 3 / 4; i += THREADS) s[i] = g[i];
    }

    // ---- fold phase: 64 threads compute K@[R|t] and K@cam ONCE per (b,v) ----
    if (tid < NB * V_NUM) {
        const int fbl = tid >> 3;       // 0..7
        const int fv  = tid & 7;        // 0..7
        const float* k  = Kmat + fv * 9;
        const float* R  = gt_R + (b0 + fbl) * (V_NUM * 9)  + fv * 9;
        const float* t  = gt_t + (b0 + fbl) * (V_NUM * 3)  + fv * 3;
        const float* cm = cam  + (b0 + fbl) * (V_NUM * 12) + fv * 12;
        float* rec = &sFold[tid * 24];
        #pragma unroll
        for (int r = 0; r < 3; r++) {
            float k0 = k[r * 3 + 0], k1 = k[r * 3 + 1], k2 = k[r * 3 + 2];
            #pragma unroll
            for (int c = 0; c < 3; c++)
                rec[r * 4 + c] = fmaf(k0, R[c], fmaf(k1, R[3 + c], k2 * R[6 + c]));
            rec[r * 4 + 3] = fmaf(k0, t[0], fmaf(k1, t[1], k2 * t[2]));
            #pragma unroll
            for (int c = 0; c < 4; c++)
                rec[12 + r * 4 + c] = fmaf(k0, cm[c], fmaf(k1, cm[4 + c], k2 * cm[8 + c]));
        }
    }
    __syncthreads();

    // ---- consumer mapping: bl | v | jh ----
    const int bl = tid >> 5;            // 0..7
    const int v  = (tid >> 2) & 7;      // 0..7
    const int jh = tid & 3;             // 0..3

    // load folded matrices from smem (broadcast among the 4 jh threads)
    float G[12], Cm[12];
    {
        const float4* rec4 = (const float4*)&sFold[((bl << 3) + v) * 24];
        #pragma unroll
        for (int i = 0; i < 3; i++) {
            float4 a = rec4[i];
            G[i * 4 + 0] = a.x; G[i * 4 + 1] = a.y; G[i * 4 + 2] = a.z; G[i * 4 + 3] = a.w;
        }
        #pragma unroll
        for (int i = 0; i < 3; i++) {
            float4 a = rec4[3 + i];
            Cm[i * 4 + 0] = a.x; Cm[i * 4 + 1] = a.y; Cm[i * 4 + 2] = a.z; Cm[i * 4 + 3] = a.w;
        }
    }

    const float4* gt4 = (const float4*)(sGT + bl * (J_NUM * 3));
    const float4* pr4 = (const float4*)(sPR + bl * (J_NUM * 3));

    float acc = 0.0f;

    // ---- main loop: this thread's 16 joints = 4 quads ----
    #pragma unroll
    for (int q = 0; q < QUADS; q++) {
        const int jq = jh * QUADS + q;
        const float4 xa = gt4[jq * 3 + 0];
        const float4 xb = gt4[jq * 3 + 1];
        const float4 xc = gt4[jq * 3 + 2];
        const float4 pa = pr4[jq * 3 + 0];
        const float4 pb = pr4[jq * 3 + 1];
        const float4 pc = pr4[jq * 3 + 2];

        const float Xs[4][3] = {{xa.x, xa.y, xa.z}, {xa.w, xb.x, xb.y},
                                {xb.z, xb.w, xc.x}, {xc.y, xc.z, xc.w}};
        const float Ps[4][3] = {{pa.x, pa.y, pa.z}, {pa.w, pb.x, pb.y},
                                {pb.z, pb.w, pc.x}, {pc.y, pc.z, pc.w}};

        #pragma unroll
        for (int s = 0; s < 4; s++) {
            const float X0 = Xs[s][0], X1 = Xs[s][1], X2 = Xs[s][2];
            const float P0 = Ps[s][0], P1 = Ps[s][1], P2 = Ps[s][2];

            float u  = fmaf(G[0], X0, fmaf(G[1], X1, fmaf(G[2],  X2, G[3])));
            float vv = fmaf(G[4], X0, fmaf(G[5], X1, fmaf(G[6],  X2, G[7])));
            float w  = fmaf(G[8], X0, fmaf(G[9], X1, fmaf(G[10], X2, G[11])));

            float up = fmaf(Cm[0], P0, fmaf(Cm[1], P1, fmaf(Cm[2],  P2, Cm[3])));
            float vp = fmaf(Cm[4], P0, fmaf(Cm[5], P1, fmaf(Cm[6],  P2, Cm[7])));
            float wp = fmaf(Cm[8], P0, fmaf(Cm[9], P1, fmaf(Cm[10], P2, Cm[11])));

            float r  = rcpa(w * wp);
            float nw = -w;
            float dx = fmaf(up, nw, u  * wp) * r;
            float dy = fmaf(vp, nw, vv * wp) * r;

            acc += smooth_term(dx * dx);
            acc += smooth_term(dy * dy);
        }
    }

    // ---- block reduction (8 warps) ----
    #pragma unroll
    for (int o = 16; o > 0; o >>= 1)
        acc += __shfl_xor_sync(0xFFFFFFFFu, acc, o);

    const int lane = tid & 31;
    const int wid  = tid >> 5;
    if (lane == 0) sWarp[wid] = acc;
    __syncthreads();

    if (wid == 0) {
        float s = (lane < THREADS / 32) ? sWarp[lane] : 0.0f;
        #pragma unroll
        for (int o = 4; o > 0; o >>= 1)
            s += __shfl_xor_sync(0xFFFFFFFFu, s, o);
        if (lane == 0) g_partials[blockIdx.x] = s;
    }

    // ---- fused finish: last-arriving block reduces partials ----
    __threadfence();
    if (tid == 0) {
        int c = atomicAdd(&g_count, 1);
        sIsLast = (c == NBLOCKS - 1);
    }
    __syncthreads();

    if (sIsLast) {
        float s = 0.0f;
        #pragma unroll
        for (int rep = 0; rep < NBLOCKS / THREADS; rep++)
            s += g_partials[tid + rep * THREADS];

        #pragma unroll
        for (int o = 16; o > 0; o >>= 1)
            s += __shfl_xor_sync(0xFFFFFFFFu, s, o);
        if (lane == 0) sWarp[wid] = s;
        __syncthreads();

        if (wid == 0) {
            float t = (lane < THREADS / 32) ? sWarp[lane] : 0.0f;
            #pragma unroll
            for (int o = 4; o > 0; o >>= 1)
                t += __shfl_xor_sync(0xFFFFFFFFu, t, o);
            if (lane == 0) {
                out[0] = t * (1.0f / (2.0f * (float)B_TOTAL));
                g_count = 0;   // reset for next graph replay
            }
        }
    }
}

extern "C" void kernel_launch(void* const* d_in, const int* in_sizes, int n_in,
                              void* d_out, int out_size)
{
    const float* gt_kps = (const float*)d_in[0];
    const float* pr_kps = (const float*)d_in[1];
    const float* gt_R   = (const float*)d_in[2];
    const float* gt_t   = (const float*)d_in[3];
    const float* Kmat   = (const float*)d_in[4];
    const float* cam    = (const float*)d_in[5];
    float* out = (float*)d_out;

    proj_loss_fused<<<NBLOCKS, THREADS>>>(gt_kps, pr_kps, gt_R, gt_t, Kmat, cam, out);
}

// round 12
// speedup vs baseline: 3.0164x; 1.1488x over previous
#include <cuda_runtime.h>

// ProjectionLoss fused single-kernel, packed-operand f32x2:
//   Thread = (b_local, view), 64 joints. Keypoints staged INTERLEAVED in smem
//   as (X0,P0,X1,P1,X2,P2) per joint -> ld.shared 16B delivers naturally packed
//   f32x2 operands (no pk2 movs, the R9 mistake). Folded matrices kept as
//   packed (G_i, C_i) u64 register pairs (12 one-time movs).
//   Matvec: 9 fma.rn.f32x2 per point-view (replaces 18 FFMA on the fma pipe,
//   which R6-R11 showed is the binding pipe). Scalar epilogue, 1 rcp/point.
//   Per-b smem stride padded to 392 floats: bl-lanes hit banks {0,8,16,24}.
//   Smooth-MSE: min(d2, ex2(fma(lg2(d2),0.1,log2(400^0.9)))), branch-free.
//   Tail: last-arriving block reduces per-block partials in fixed order.

#define B_TOTAL 16384
#define V_NUM   8
#define J_NUM   64
#define NB      16                      // batch elements per block
#define THREADS (NB * V_NUM)            // 128
#define NBLOCKS (B_TOTAL / NB)          // 1024

#define XPSTR   392                     // padded floats per b (384 + 8 pad)

#define LOG2_POWC 7.77947056f           // log2(400^0.9)

__device__ float g_partials[NBLOCKS];
__device__ int   g_count = 0;

typedef unsigned long long u64;

__device__ __forceinline__ u64 pk2(float lo, float hi) {
    u64 r; asm("mov.b64 %0, {%1, %2};" : "=l"(r) : "f"(lo), "f"(hi)); return r;
}
__device__ __forceinline__ void upk2(float& lo, float& hi, u64 v) {
    asm("mov.b64 {%0, %1}, %2;" : "=f"(lo), "=f"(hi) : "l"(v));
}
__device__ __forceinline__ u64 fma2(u64 a, u64 b, u64 c) {
    u64 d; asm("fma.rn.f32x2 %0, %1, %2, %3;" : "=l"(d) : "l"(a), "l"(b), "l"(c)); return d;
}
__device__ __forceinline__ float rcpa(float x) {
    float r; asm("rcp.approx.f32 %0, %1;" : "=f"(r) : "f"(x)); return r;
}
__device__ __forceinline__ float lg2a(float x) {
    float r; asm("lg2.approx.f32 %0, %1;" : "=f"(r) : "f"(x)); return r;
}
__device__ __forceinline__ float ex2a(float x) {
    float r; asm("ex2.approx.f32 %0, %1;" : "=f"(r) : "f"(x)); return r;
}
__device__ __forceinline__ float smooth_term(float d2) {
    // exact rewrite of: d2>400 ? d2^0.1 * 400^0.9 : d2 (pow branch >= d2 iff d2<=400)
    float p = ex2a(fmaf(lg2a(d2), 0.1f, LOG2_POWC));
    return fminf(d2, p);
}

__global__ __launch_bounds__(THREADS, 8)
void proj_loss_fused(const float* __restrict__ gt_kps,
                     const float* __restrict__ pr_kps,
                     const float* __restrict__ gt_R,
                     const float* __restrict__ gt_t,
                     const float* __restrict__ Kmat,
                     const float* __restrict__ cam,
                     float* __restrict__ out)
{
    __shared__ __align__(16) float sXP[NB * XPSTR];   // 6272 floats, interleaved X/P
    __shared__ float sWarp[THREADS / 32];
    __shared__ int   sIsLast;

    const int tid = threadIdx.x;
    const long b0 = (long)blockIdx.x * NB;

    // ---- stage keypoints INTERLEAVED: sXP[b][2e]=gt[e], [2e+1]=pr[e] ----
    // 48 float4 per b per array; float4 i never straddles a b boundary.
    {
        const float4* g4 = (const float4*)(gt_kps + b0 * (J_NUM * 3));
        const float4* p4 = (const float4*)(pr_kps + b0 * (J_NUM * 3));
        for (int i = tid; i < NB * J_NUM * 3 / 4; i += THREADS) {
            const int b  = i / 48;          // 48 float4 per batch element
            const int iw = i - b * 48;
            float4 g = g4[i];
            float4 p = p4[i];
            float4* dst = (float4*)(sXP + b * XPSTR) + 2 * iw;
            dst[0] = make_float4(g.x, p.x, g.y, p.y);
            dst[1] = make_float4(g.z, p.z, g.w, p.w);
        }
    }

    // ---- per-thread fold from GLOBAL: packed (gt_coeff, pred_coeff) pairs ----
    const int bl = tid >> 3;            // 0..15
    const int v  = tid & 7;             // 0..7

    u64 GC[12];
    {
        const float* k  = Kmat + v * 9;
        const float* R  = gt_R + (b0 + bl) * (V_NUM * 9)  + v * 9;
        const float* t  = gt_t + (b0 + bl) * (V_NUM * 3)  + v * 3;
        const float* cm = cam  + (b0 + bl) * (V_NUM * 12) + v * 12;
        #pragma unroll
        for (int r = 0; r < 3; r++) {
            float k0 = k[r * 3 + 0], k1 = k[r * 3 + 1], k2 = k[r * 3 + 2];
            #pragma unroll
            for (int c = 0; c < 3; c++) {
                float g = fmaf(k0, R[c], fmaf(k1, R[3 + c], k2 * R[6 + c]));
                float p = fmaf(k0, cm[c], fmaf(k1, cm[4 + c], k2 * cm[8 + c]));
                GC[r * 4 + c] = pk2(g, p);
            }
            float g3 = fmaf(k0, t[0], fmaf(k1, t[1], k2 * t[2]));
            float p3 = fmaf(k0, cm[3], fmaf(k1, cm[7], k2 * cm[11]));
            GC[r * 4 + 3] = pk2(g3, p3);
        }
    }

    __syncthreads();

    // per-b base, in ulonglong2 units (16B): XPSTR/4 = 98 per b, 3 u64 per joint
    const ulonglong2* xp2 = (const ulonglong2*)(sXP) + bl * (XPSTR / 4);

    float acc = 0.0f;

    // ---- main loop: 32 joint-pairs; operands arrive packed from smem ----
    #pragma unroll 2
    for (int jp = 0; jp < J_NUM / 2; jp++) {
        const ulonglong2 qa = xp2[jp * 3 + 0];   // (X0P0, X1P1)   joint A
        const ulonglong2 qb = xp2[jp * 3 + 1];   // (X2P2 A, X0P0 B)
        const ulonglong2 qc = xp2[jp * 3 + 2];   // (X1P1 B, X2P2 B)

        #pragma unroll
        for (int s = 0; s < 2; s++) {
            const u64 x0 = (s == 0) ? qa.x : qb.y;
            const u64 x1 = (s == 0) ? qa.y : qc.x;
            const u64 x2 = (s == 0) ? qb.x : qc.y;

            u64 uu = fma2(GC[0], x0, fma2(GC[1], x1, fma2(GC[2],  x2, GC[3])));
            u64 vv = fma2(GC[4], x0, fma2(GC[5], x1, fma2(GC[6],  x2, GC[7])));
            u64 ww = fma2(GC[8], x0, fma2(GC[9], x1, fma2(GC[10], x2, GC[11])));

            float u, up;  upk2(u, up, uu);
            float vl, vp; upk2(vl, vp, vv);
            float w, wp;  upk2(w, wp, ww);

            float r  = rcpa(w * wp);
            float nw = -w;
            float dx = fmaf(up, nw, u  * wp) * r;
            float dy = fmaf(vp, nw, vl * wp) * r;

            acc += smooth_term(dx * dx);
            acc += smooth_term(dy * dy);
        }
    }

    // ---- block reduction (4 warps) ----
    #pragma unroll
    for (int o = 16; o > 0; o >>= 1)
        acc += __shfl_xor_sync(0xFFFFFFFFu, acc, o);

    const int lane = tid & 31;
    const int wid  = tid >> 5;
    if (lane == 0) sWarp[wid] = acc;
    __syncthreads();

    if (wid == 0) {
        float s = (lane < THREADS / 32) ? sWarp[lane] : 0.0f;
        #pragma unroll
        for (int o = 2; o > 0; o >>= 1)
            s += __shfl_xor_sync(0xFFFFFFFFu, s, o);
        if (lane == 0) g_partials[blockIdx.x] = s;
    }

    // ---- fused finish: last-arriving block reduces partials ----
    __threadfence();
    if (tid == 0) {
        int c = atomicAdd(&g_count, 1);
        sIsLast = (c == NBLOCKS - 1);
    }
    __syncthreads();

    if (sIsLast) {
        float s = 0.0f;
        #pragma unroll
        for (int rep = 0; rep < NBLOCKS / THREADS; rep++)
            s += g_partials[tid + rep * THREADS];

        #pragma unroll
        for (int o = 16; o > 0; o >>= 1)
            s += __shfl_xor_sync(0xFFFFFFFFu, s, o);
        if (lane == 0) sWarp[wid] = s;
        __syncthreads();

        if (wid == 0) {
            float t = (lane < THREADS / 32) ? sWarp[lane] : 0.0f;
            #pragma unroll
            for (int o = 2; o > 0; o >>= 1)
                t += __shfl_xor_sync(0xFFFFFFFFu, t, o);
            if (lane == 0) {
                out[0] = t * (1.0f / (2.0f * (float)B_TOTAL));
                g_count = 0;   // reset for next graph replay
            }
        }
    }
}

extern "C" void kernel_launch(void* const* d_in, const int* in_sizes, int n_in,
                              void* d_out, int out_size)
{
    const float* gt_kps = (const float*)d_in[0];
    const float* pr_kps = (const float*)d_in[1];
    const float* gt_R   = (const float*)d_in[2];
    const float* gt_t   = (const float*)d_in[3];
    const float* Kmat   = (const float*)d_in[4];
    const float* cam    = (const float*)d_in[5];
    float* out = (float*)d_out;

    proj_loss_fused<<<NBLOCKS, THREADS>>>(gt_kps, pr_kps, gt_R, gt_t, Kmat, cam, out);
}

// round 13
// speedup vs baseline: 3.0240x; 1.0025x over previous
#include <cuda_runtime.h>

// ProjectionLoss fused single-kernel: packed-operand f32x2 + shared-fold j-split.
//   Block = 8 batch x 128 threads. Thread = (b_local, view, j-half): 32 joints.
//   - Keypoints staged INTERLEAVED in smem (X0,P0,X1,P1,X2,P2 per joint):
//     ld.shared 16B delivers naturally packed f32x2 operands (R12, -16% instr).
//   - K-folded matrices computed ONCE per (b,view) by 64 folder threads into
//     smem as packed (gt,pred) float2 pairs; consumers recover GC[12] with
//     6 broadcast LDS.128 (no duplicated fold work - the R7/R8 mistake).
//   - Matvec: 9 fma.rn.f32x2 per point-view. Scalar epilogue, 1 rcp/point.
//   - 2048 blocks x 128 thr = 262k threads: 2x R12's warps to fix the
//     latency-boundedness (issue 54% @ occ 34%) its lower instr count exposed.
//   - Smooth-MSE: min(d2, ex2(fma(lg2(d2),0.1,log2(400^0.9)))), branch-free.
//   - Tail: last-arriving block reduces per-block partials in fixed order.

#define B_TOTAL 16384
#define V_NUM   8
#define J_NUM   64
#define NB      8                       // batch elements per block
#define JSPLIT  2                       // j-split threads per (b,view)
#define THREADS (NB * V_NUM * JSPLIT)   // 128
#define NBLOCKS (B_TOTAL / NB)          // 2048
#define JPAIRS  (J_NUM / 2 / JSPLIT)    // 16 joint-pairs per thread

#define XPSTR   392                     // padded floats per b (384 + 8 pad)

#define LOG2_POWC 7.77947056f           // log2(400^0.9)

__device__ float g_partials[NBLOCKS];
__device__ int   g_count = 0;

typedef unsigned long long u64;

__device__ __forceinline__ void upk2(float& lo, float& hi, u64 v) {
    asm("mov.b64 {%0, %1}, %2;" : "=f"(lo), "=f"(hi) : "l"(v));
}
__device__ __forceinline__ u64 fma2(u64 a, u64 b, u64 c) {
    u64 d; asm("fma.rn.f32x2 %0, %1, %2, %3;" : "=l"(d) : "l"(a), "l"(b), "l"(c)); return d;
}
__device__ __forceinline__ float rcpa(float x) {
    float r; asm("rcp.approx.f32 %0, %1;" : "=f"(r) : "f"(x)); return r;
}
__device__ __forceinline__ float lg2a(float x) {
    float r; asm("lg2.approx.f32 %0, %1;" : "=f"(r) : "f"(x)); return r;
}
__device__ __forceinline__ float ex2a(float x) {
    float r; asm("ex2.approx.f32 %0, %1;" : "=f"(r) : "f"(x)); return r;
}
__device__ __forceinline__ float smooth_term(float d2) {
    // exact rewrite of: d2>400 ? d2^0.1 * 400^0.9 : d2 (pow branch >= d2 iff d2<=400)
    float p = ex2a(fmaf(lg2a(d2), 0.1f, LOG2_POWC));
    return fminf(d2, p);
}

__global__ __launch_bounds__(THREADS, 8)
void proj_loss_fused(const float* __restrict__ gt_kps,
                     const float* __restrict__ pr_kps,
                     const float* __restrict__ gt_R,
                     const float* __restrict__ gt_t,
                     const float* __restrict__ Kmat,
                     const float* __restrict__ cam,
                     float* __restrict__ out)
{
    __shared__ __align__(16) float sXP[NB * XPSTR];          // 3136 floats
    __shared__ __align__(16) float sFold[NB * V_NUM * 24];   // 1536 (12 f32x2/record)
    __shared__ float sWarp[THREADS / 32];
    __shared__ int   sIsLast;

    const int tid = threadIdx.x;
    const long b0 = (long)blockIdx.x * NB;

    // ---- stage keypoints INTERLEAVED: per joint (X0,P0)(X1,P1)(X2,P2) ----
    {
        const float4* g4 = (const float4*)(gt_kps + b0 * (J_NUM * 3));
        const float4* p4 = (const float4*)(pr_kps + b0 * (J_NUM * 3));
        for (int i = tid; i < NB * J_NUM * 3 / 4; i += THREADS) {
            const int b  = i / 48;          // 48 float4 per batch element
            const int iw = i - b * 48;
            float4 g = g4[i];
            float4 p = p4[i];
            float4* dst = (float4*)(sXP + b * XPSTR) + 2 * iw;
            dst[0] = make_float4(g.x, p.x, g.y, p.y);
            dst[1] = make_float4(g.z, p.z, g.w, p.w);
        }
    }

    // ---- fold phase: 64 threads, ONE fold per (b,v), packed (g,p) pairs ----
    if (tid < NB * V_NUM) {
        const int fbl = tid >> 3;       // 0..7
        const int fv  = tid & 7;        // 0..7
        const float* k  = Kmat + fv * 9;
        const float* R  = gt_R + (b0 + fbl) * (V_NUM * 9)  + fv * 9;
        const float* t  = gt_t + (b0 + fbl) * (V_NUM * 3)  + fv * 3;
        const float* cm = cam  + (b0 + fbl) * (V_NUM * 12) + fv * 12;
        float2* rec = (float2*)&sFold[tid * 24];
        #pragma unroll
        for (int r = 0; r < 3; r++) {
            float k0 = k[r * 3 + 0], k1 = k[r * 3 + 1], k2 = k[r * 3 + 2];
            #pragma unroll
            for (int c = 0; c < 3; c++) {
                float g = fmaf(k0, R[c], fmaf(k1, R[3 + c], k2 * R[6 + c]));
                float p = fmaf(k0, cm[c], fmaf(k1, cm[4 + c], k2 * cm[8 + c]));
                rec[r * 4 + c] = make_float2(g, p);
            }
            float g3 = fmaf(k0, t[0], fmaf(k1, t[1], k2 * t[2]));
            float p3 = fmaf(k0, cm[3], fmaf(k1, cm[7], k2 * cm[11]));
            rec[r * 4 + 3] = make_float2(g3, p3);
        }
    }
    __syncthreads();

    // ---- consumer mapping: bl | v | jh ----
    const int bl = tid >> 4;            // 0..7
    const int v  = (tid >> 1) & 7;      // 0..7
    const int jh = tid & 1;             // 0..1

    // recover packed GC[12] via 6 broadcast LDS.128
    u64 GC[12];
    {
        const ulonglong2* f2 = (const ulonglong2*)&sFold[((bl << 3) + v) * 24];
        #pragma unroll
        for (int i = 0; i < 6; i++) {
            ulonglong2 q = f2[i];
            GC[i * 2 + 0] = q.x;
            GC[i * 2 + 1] = q.y;
        }
    }

    // per-b base in 16B units; 3 ulonglong2 per joint-pair
    const ulonglong2* xp2 = (const ulonglong2*)(sXP) + bl * (XPSTR / 4);

    float acc = 0.0f;

    // ---- main loop: 16 joint-pairs; operands arrive packed from smem ----
    #pragma unroll 4
    for (int q = 0; q < JPAIRS; q++) {
        const int jp = jh * JPAIRS + q;
        const ulonglong2 qa = xp2[jp * 3 + 0];   // (X0P0 A, X1P1 A)
        const ulonglong2 qb = xp2[jp * 3 + 1];   // (X2P2 A, X0P0 B)
        const ulonglong2 qc = xp2[jp * 3 + 2];   // (X1P1 B, X2P2 B)

        #pragma unroll
        for (int s = 0; s < 2; s++) {
            const u64 x0 = (s == 0) ? qa.x : qb.y;
            const u64 x1 = (s == 0) ? qa.y : qc.x;
            const u64 x2 = (s == 0) ? qb.x : qc.y;

            u64 uu = fma2(GC[0], x0, fma2(GC[1], x1, fma2(GC[2],  x2, GC[3])));
            u64 vv = fma2(GC[4], x0, fma2(GC[5], x1, fma2(GC[6],  x2, GC[7])));
            u64 ww = fma2(GC[8], x0, fma2(GC[9], x1, fma2(GC[10], x2, GC[11])));

            float u, up;  upk2(u, up, uu);
            float vl, vp; upk2(vl, vp, vv);
            float w, wp;  upk2(w, wp, ww);

            float r  = rcpa(w * wp);
            float nw = -w;
            float dx = fmaf(up, nw, u  * wp) * r;
            float dy = fmaf(vp, nw, vl * wp) * r;

            acc += smooth_term(dx * dx);
            acc += smooth_term(dy * dy);
        }
    }

    // ---- block reduction (4 warps) ----
    #pragma unroll
    for (int o = 16; o > 0; o >>= 1)
        acc += __shfl_xor_sync(0xFFFFFFFFu, acc, o);

    const int lane = tid & 31;
    const int wid  = tid >> 5;
    if (lane == 0) sWarp[wid] = acc;
    __syncthreads();

    if (wid == 0) {
        float s = (lane < THREADS / 32) ? sWarp[lane] : 0.0f;
        #pragma unroll
        for (int o = 2; o > 0; o >>= 1)
            s += __shfl_xor_sync(0xFFFFFFFFu, s, o);
        if (lane == 0) g_partials[blockIdx.x] = s;
    }

    // ---- fused finish: last-arriving block reduces partials ----
    __threadfence();
    if (tid == 0) {
        int c = atomicAdd(&g_count, 1);
        sIsLast = (c == NBLOCKS - 1);
    }
    __syncthreads();

    if (sIsLast) {
        float s = 0.0f;
        #pragma unroll
        for (int rep = 0; rep < NBLOCKS / THREADS; rep++)
            s += g_partials[tid + rep * THREADS];

        #pragma unroll
        for (int o = 16; o > 0; o >>= 1)
            s += __shfl_xor_sync(0xFFFFFFFFu, s, o);
        if (lane == 0) sWarp[wid] = s;
        __syncthreads();

        if (wid == 0) {
            float t = (lane < THREADS / 32) ? sWarp[lane] : 0.0f;
            #pragma unroll
            for (int o = 2; o > 0; o >>= 1)
                t += __shfl_xor_sync(0xFFFFFFFFu, t, o);
            if (lane == 0) {
                out[0] = t * (1.0f / (2.0f * (float)B_TOTAL));
                g_count = 0;   // reset for next graph replay
            }
        }
    }
}

extern "C" void kernel_launch(void* const* d_in, const int* in_sizes, int n_in,
                              void* d_out, int out_size)
{
    const float* gt_kps = (const float*)d_in[0];
    const float* pr_kps = (const float*)d_in[1];
    const float* gt_R   = (const float*)d_in[2];
    const float* gt_t   = (const float*)d_in[3];
    const float* Kmat   = (const float*)d_in[4];
    const float* cam    = (const float*)d_in[5];
    float* out = (float*)d_out;

    proj_loss_fused<<<NBLOCKS, THREADS>>>(gt_kps, pr_kps, gt_R, gt_t, Kmat, cam, out);
}